// round 11
// baseline (speedup 1.0000x reference)
#include <cuda_runtime.h>
#include <cuda_fp16.h>
#include <cstdint>

// Problem shape (fixed by the dataset)
constexpr int B = 8, C = 16, H = 512, W = 512;
constexpr int HW = H * W;            // 262144 = 2^18
constexpr int CHW = C * HW;
constexpr int NPIX = B * HW;         // 2,097,152
constexpr int NOUT = B * CHW;        // 33,554,432

// Split-plane fp16 scratch, 64 MiB total (R10 layout):
//   plane LO = channels 0..7  : pixel p at 16B offset p*16
//   plane HI = channels 8..15 : same indexing, +32 MiB
__device__ __half g_scratch[NOUT];
constexpr size_t HI_OFF_H2 = (size_t)NPIX * 4;   // half2 offset of HI plane

// --- PDL primitives (sm_90+) -----------------------------------------------
__device__ __forceinline__ void pdl_trigger() {
    asm volatile("griddepcontrol.launch_dependents;");
}
__device__ __forceinline__ void pdl_wait() {
    asm volatile("griddepcontrol.wait;" ::: "memory");
}

// ---------------------------------------------------------------------------
// 16-byte fp16 vector reduction (hard max RED width): 8 halves per request.
// ---------------------------------------------------------------------------
__device__ __forceinline__ void red_v4h2(__half2* p, __half2 a, __half2 b,
                                         __half2 c, __half2 d) {
    unsigned ra = *(unsigned*)&a, rb = *(unsigned*)&b;
    unsigned rc = *(unsigned*)&c, rd = *(unsigned*)&d;
    asm volatile("red.global.add.noftz.v4.f16x2 [%0], {%1, %2, %3, %4};"
                 :: "l"(p), "r"(ra), "r"(rb), "r"(rc), "r"(rd) : "memory");
}

// ---------------------------------------------------------------------------
// Zero the scratch. Single wave (1024 blocks x 256 threads, grid-stride),
// triggers dependents at ENTRY so splat(0) launches immediately and overlaps
// its x/grid prologue loads with the zeroing.
// ---------------------------------------------------------------------------
__global__ __launch_bounds__(256)
void zero_kernel(uint4* __restrict__ p) {
    pdl_trigger();
    const uint4 z = make_uint4(0u, 0u, 0u, 0u);
    constexpr int N16 = NOUT * 2 / 16;          // 4,194,304 uint4
    for (int i = blockIdx.x * 256 + threadIdx.x; i < N16; i += 1024 * 256)
        p[i] = z;
}

// ---------------------------------------------------------------------------
// Per-batch inverse bilinear splat (R10 body).
// wait_primary=1 (batch 0 only): front-load x/grid reads + math, then
// griddepcontrol.wait before the first RED so zeroing is complete.
// Batches 1..7 launch while the previous transpose runs (no dependence).
// Never triggers early -> its transpose launches at completion.
// ---------------------------------------------------------------------------
__global__ __launch_bounds__(256)
void splat_kernel(const float* __restrict__ x,
                  const float2* __restrict__ grid,
                  int b, int wait_primary) {
    int hw = blockIdx.x * 256 + threadIdx.x;    // 0 .. HW-1

    float2 g = __ldcs(grid + (size_t)b * HW + hw);   // single-use: evict-first

    float gi = fminf(fmaxf((g.x + 1.0f) * 0.5f * (float)H + 1.0f, 0.0f), (float)(H + 1));
    float gj = fminf(fmaxf((g.y + 1.0f) * 0.5f * (float)W + 1.0f, 0.0f), (float)(W + 1));

    int   fi  = (int)gi;            // gi >= 0 so trunc == floor
    int   fj  = (int)gj;
    float fri = gi - (float)fi;
    float frj = gj - (float)fj;

    float w00 = (1.0f - fri) * (1.0f - frj);
    float w01 = (1.0f - fri) * frj;
    float w10 = fri * (1.0f - frj);
    float w11 = fri * frj;

    int oi0 = fi - 1;
    int oj0 = fj - 1;
    bool i0 = (unsigned)oi0       < (unsigned)H;
    bool i1 = (unsigned)(oi0 + 1) < (unsigned)H;
    bool j0 = (unsigned)oj0       < (unsigned)W;
    bool j1 = (unsigned)(oj0 + 1) < (unsigned)W;

    // 16 channel values, coalesced per channel, streaming (single use)
    const float* xp = x + (size_t)b * CHW + hw;
    float v[C];
#pragma unroll
    for (int c = 0; c < C; c++) v[c] = __ldcs(xp + c * HW);

    // Plane pointers for corner (oi0, oj0); pixel stride = 4 half2 (16B).
    size_t p00 = (size_t)b * HW + (size_t)oi0 * W + oj0;
    __half2* l00 = (__half2*)g_scratch + p00 * 4;              // LO, (i0,j0)
    __half2* l10 = l00 + (size_t)W * 4;                        // LO, (i1,j0)
    __half2* h00 = (__half2*)g_scratch + HI_OFF_H2 + p00 * 4;  // HI: +32MB
    __half2* h10 = h00 + (size_t)W * 4;

#define PACK4(dst, wgt, half)                                                   \
    {                                                                           \
        _Pragma("unroll")                                                       \
        for (int j = 0; j < 4; j++)                                             \
            dst[j] = __floats2half2_rn(v[8*(half) + 2*j]     * (wgt),           \
                                       v[8*(half) + 2*j + 1] * (wgt));          \
    }

    // Batch 0: ensure the zero pass is complete before the first RED.
    if (wait_primary) pdl_wait();

    if (j0) {   // corners (i0,j0)/(i1,j0): plane- and i-alternated issue
        __half2 a[4], c[4];
        if (i0) { PACK4(a, w00, 0); red_v4h2(l00, a[0], a[1], a[2], a[3]); }
        if (i1) { PACK4(c, w10, 0); red_v4h2(l10, c[0], c[1], c[2], c[3]); }
        if (i0) { PACK4(a, w00, 1); red_v4h2(h00, a[0], a[1], a[2], a[3]); }
        if (i1) { PACK4(c, w10, 1); red_v4h2(h10, c[0], c[1], c[2], c[3]); }
    }
    if (j1) {   // corners (i0,j1)/(i1,j1): next pixel = +4 half2 (16B)
        __half2 a[4], c[4];
        if (i0) { PACK4(a, w01, 0); red_v4h2(l00 + 4, a[0], a[1], a[2], a[3]); }
        if (i1) { PACK4(c, w11, 0); red_v4h2(l10 + 4, c[0], c[1], c[2], c[3]); }
        if (i0) { PACK4(a, w01, 1); red_v4h2(h00 + 4, a[0], a[1], a[2], a[3]); }
        if (i1) { PACK4(c, w11, 1); red_v4h2(h10 + 4, c[0], c[1], c[2], c[3]); }
    }
#undef PACK4
}

// ---------------------------------------------------------------------------
// Per-batch transpose: split-plane fp16 scratch -> f32 out (C,H,W) slice.
// Launches at splat(b) completion; triggers dependents at ENTRY so that
// splat(b+1) (LSU-RED-bound) runs concurrently with this kernel's DRAM
// writes. Disjoint data from everything concurrent with it.
// ---------------------------------------------------------------------------
__global__ __launch_bounds__(128)
void transpose_kernel(const __half2* __restrict__ s, float* __restrict__ out,
                      int b) {
    pdl_trigger();                   // release splat(b+1) immediately
    pdl_wait();                      // primary (splat b) already complete

    __shared__ __half2 sm[8][512];   // sm[r][p] = channels (2r,2r+1), pixel p

    int base = blockIdx.x * 512;     // pixel base within batch
    int t = threadIdx.x;

#pragma unroll
    for (int q = 0; q < 4; q++) {
        int p = t + 128 * q;
        size_t gp = (size_t)b * HW + base + p;
        uint4 a  = __ldcs((const uint4*)(s + gp * 4));               // ch 0..7
        uint4 bq = __ldcs((const uint4*)(s + HI_OFF_H2 + gp * 4));   // ch 8..15
        sm[0][p] = *(__half2*)&a.x;  sm[1][p] = *(__half2*)&a.y;
        sm[2][p] = *(__half2*)&a.z;  sm[3][p] = *(__half2*)&a.w;
        sm[4][p] = *(__half2*)&bq.x; sm[5][p] = *(__half2*)&bq.y;
        sm[6][p] = *(__half2*)&bq.z; sm[7][p] = *(__half2*)&bq.w;
    }
    __syncthreads();

    float* ob = out + (size_t)b * CHW + base;

#pragma unroll
    for (int r = 0; r < 8; r++) {
        uint4 raw = *(const uint4*)&sm[r][4 * t];   // 4 half2 of channel pair r
        float2 f0 = __half22float2(*(__half2*)&raw.x);
        float2 f1 = __half22float2(*(__half2*)&raw.y);
        float2 f2 = __half22float2(*(__half2*)&raw.z);
        float2 f3 = __half22float2(*(__half2*)&raw.w);
        float4 ve = make_float4(f0.x, f1.x, f2.x, f3.x);  // channel 2r
        float4 vo = make_float4(f0.y, f1.y, f2.y, f3.y);  // channel 2r+1
        __stcs((float4*)(ob + (size_t)(2*r)     * HW) + t, ve);
        __stcs((float4*)(ob + (size_t)(2*r + 1) * HW) + t, vo);
    }
}

extern "C" void kernel_launch(void* const* d_in, const int* in_sizes, int n_in,
                              void* d_out, int out_size) {
    const float*  x    = (const float*)d_in[0];
    const float2* grid = (const float2*)d_in[1];
    float*        out  = (float*)d_out;

    static __half* scratch_ptr = nullptr;
    if (!scratch_ptr) cudaGetSymbolAddress((void**)&scratch_ptr, g_scratch);

    // Launch config with programmatic dependent launch (PDL) attribute:
    // each launch may start as soon as its stream predecessor triggers
    // griddepcontrol.launch_dependents (or completes).
    cudaLaunchAttribute attr[1];
    attr[0].id = cudaLaunchAttributeProgrammaticStreamSerialization;
    attr[0].val.programmaticStreamSerializationAllowed = 1;

    cudaLaunchConfig_t cfg{};
    cfg.stream   = 0;
    cfg.attrs    = attr;
    cfg.numAttrs = 1;

    // 1) zero scratch (plain launch; triggers dependents at entry)
    zero_kernel<<<1024, 256>>>((uint4*)scratch_ptr);

    // 2) PDL chain: s0, t0, s1, t1, ... s7, t7
    //    t_b launches at s_b completion (s_b never triggers early).
    //    s_{b+1} launches at t_b entry-trigger -> overlaps t_b's DRAM phase.
    for (int b = 0; b < B; b++) {
        cfg.gridDim  = dim3(HW / 256);
        cfg.blockDim = dim3(256);
        cudaLaunchKernelEx(&cfg, splat_kernel, x, grid, b, (int)(b == 0));

        cfg.gridDim  = dim3(HW / 512);
        cfg.blockDim = dim3(128);
        cudaLaunchKernelEx(&cfg, transpose_kernel,
                           (const __half2*)scratch_ptr, out, b);
    }
}

// round 12
// speedup vs baseline: 1.1405x; 1.1405x over previous
#include <cuda_runtime.h>
#include <cuda_fp16.h>
#include <cstdint>

// Problem shape (fixed by the dataset)
constexpr int B = 8, C = 16, H = 512, W = 512;
constexpr int HW = H * W;            // 262144 = 2^18
constexpr int CHW = C * HW;
constexpr int NPIX = B * HW;         // 2,097,152
constexpr int NOUT = B * CHW;        // 33,554,432

// Chunking: 2 chunks x 4 batches. Splat chunk grid = 4096 blocks (fills chip).
constexpr int BCHUNK = 4;
constexpr int CHUNK_PIX = BCHUNK * HW;          // 1,048,576

// Split-plane fp16 scratch, 64 MiB total (R10 layout):
//   plane LO = channels 0..7  : pixel p at 16B offset p*16
//   plane HI = channels 8..15 : same indexing, +32 MiB
__device__ __half g_scratch[NOUT];
constexpr size_t HI_OFF_H2 = (size_t)NPIX * 4;   // half2 offset of HI plane

// --- PDL primitives (sm_90+) -----------------------------------------------
__device__ __forceinline__ void pdl_trigger() {
    asm volatile("griddepcontrol.launch_dependents;");
}
__device__ __forceinline__ void pdl_wait() {
    asm volatile("griddepcontrol.wait;" ::: "memory");
}

// ---------------------------------------------------------------------------
// 16-byte fp16 vector reduction (hard max RED width): 8 halves per request.
// ---------------------------------------------------------------------------
__device__ __forceinline__ void red_v4h2(__half2* p, __half2 a, __half2 b,
                                         __half2 c, __half2 d) {
    unsigned ra = *(unsigned*)&a, rb = *(unsigned*)&b;
    unsigned rc = *(unsigned*)&c, rd = *(unsigned*)&d;
    asm volatile("red.global.add.noftz.v4.f16x2 [%0], {%1, %2, %3, %4};"
                 :: "l"(p), "r"(ra), "r"(rb), "r"(rc), "r"(rd) : "memory");
}

// ---------------------------------------------------------------------------
// Zero the scratch. Triggers dependents at ENTRY so splat chunk 0 launches
// immediately and overlaps its x/grid prologue loads with the zeroing.
// ---------------------------------------------------------------------------
__global__ __launch_bounds__(256)
void zero_kernel(uint4* __restrict__ p) {
    pdl_trigger();
    const uint4 z = make_uint4(0u, 0u, 0u, 0u);
    constexpr int N16 = NOUT * 2 / 16;          // 4,194,304 uint4
    for (int i = blockIdx.x * 256 + threadIdx.x; i < N16; i += 2048 * 256)
        p[i] = z;
}

// ---------------------------------------------------------------------------
// Splat one 4-batch chunk (grid 4096 -> full chip). R10 body.
// Chunk 0 front-loads x/grid reads + math, then griddepcontrol.wait before
// the first RED (zeroing complete). Chunk 1 needs no wait: it launches at
// T0's entry-trigger and touches only batches 4..7 (disjoint from T0's 0..3).
// Never triggers early -> its transpose launches at completion.
// ---------------------------------------------------------------------------
__global__ __launch_bounds__(256)
void splat_kernel(const float* __restrict__ x,
                  const float2* __restrict__ grid,
                  int b_base, int wait_primary) {
    int idx = blockIdx.x * 256 + threadIdx.x;   // 0 .. CHUNK_PIX-1

    int b  = b_base + (idx >> 18);              // batch
    int hw = idx & (HW - 1);

    float2 g = __ldcs(grid + (size_t)b * HW + hw);   // single-use: evict-first

    float gi = fminf(fmaxf((g.x + 1.0f) * 0.5f * (float)H + 1.0f, 0.0f), (float)(H + 1));
    float gj = fminf(fmaxf((g.y + 1.0f) * 0.5f * (float)W + 1.0f, 0.0f), (float)(W + 1));

    int   fi  = (int)gi;            // gi >= 0 so trunc == floor
    int   fj  = (int)gj;
    float fri = gi - (float)fi;
    float frj = gj - (float)fj;

    float w00 = (1.0f - fri) * (1.0f - frj);
    float w01 = (1.0f - fri) * frj;
    float w10 = fri * (1.0f - frj);
    float w11 = fri * frj;

    int oi0 = fi - 1;
    int oj0 = fj - 1;
    bool i0 = (unsigned)oi0       < (unsigned)H;
    bool i1 = (unsigned)(oi0 + 1) < (unsigned)H;
    bool j0 = (unsigned)oj0       < (unsigned)W;
    bool j1 = (unsigned)(oj0 + 1) < (unsigned)W;

    // 16 channel values, coalesced per channel, streaming (single use)
    const float* xp = x + (size_t)b * CHW + hw;
    float v[C];
#pragma unroll
    for (int c = 0; c < C; c++) v[c] = __ldcs(xp + c * HW);

    // Plane pointers for corner (oi0, oj0); pixel stride = 4 half2 (16B).
    size_t p00 = (size_t)b * HW + (size_t)oi0 * W + oj0;
    __half2* l00 = (__half2*)g_scratch + p00 * 4;              // LO, (i0,j0)
    __half2* l10 = l00 + (size_t)W * 4;                        // LO, (i1,j0)
    __half2* h00 = (__half2*)g_scratch + HI_OFF_H2 + p00 * 4;  // HI: +32MB
    __half2* h10 = h00 + (size_t)W * 4;

#define PACK4(dst, wgt, half)                                                   \
    {                                                                           \
        _Pragma("unroll")                                                       \
        for (int j = 0; j < 4; j++)                                             \
            dst[j] = __floats2half2_rn(v[8*(half) + 2*j]     * (wgt),           \
                                       v[8*(half) + 2*j + 1] * (wgt));          \
    }

    // Chunk 0: ensure the zero pass is complete before the first RED.
    if (wait_primary) pdl_wait();

    if (j0) {   // corners (i0,j0)/(i1,j0): plane- and i-alternated issue
        __half2 a[4], c[4];
        if (i0) { PACK4(a, w00, 0); red_v4h2(l00, a[0], a[1], a[2], a[3]); }
        if (i1) { PACK4(c, w10, 0); red_v4h2(l10, c[0], c[1], c[2], c[3]); }
        if (i0) { PACK4(a, w00, 1); red_v4h2(h00, a[0], a[1], a[2], a[3]); }
        if (i1) { PACK4(c, w10, 1); red_v4h2(h10, c[0], c[1], c[2], c[3]); }
    }
    if (j1) {   // corners (i0,j1)/(i1,j1): next pixel = +4 half2 (16B)
        __half2 a[4], c[4];
        if (i0) { PACK4(a, w01, 0); red_v4h2(l00 + 4, a[0], a[1], a[2], a[3]); }
        if (i1) { PACK4(c, w11, 0); red_v4h2(l10 + 4, c[0], c[1], c[2], c[3]); }
        if (i0) { PACK4(a, w01, 1); red_v4h2(h00 + 4, a[0], a[1], a[2], a[3]); }
        if (i1) { PACK4(c, w11, 1); red_v4h2(h10 + 4, c[0], c[1], c[2], c[3]); }
    }
#undef PACK4
}

// ---------------------------------------------------------------------------
// Transpose one 4-batch chunk: split-plane fp16 scratch -> f32 out.
// Launches at its splat chunk's completion; triggers dependents at ENTRY so
// the NEXT splat chunk (disjoint batches) overlaps this kernel's DRAM writes.
// ---------------------------------------------------------------------------
__global__ __launch_bounds__(128)
void transpose_kernel(const __half2* __restrict__ s, float* __restrict__ out,
                      int b_base) {
    pdl_trigger();                   // release the next splat chunk now
    pdl_wait();                      // primary (our splat chunk) is complete

    __shared__ __half2 sm[8][512];   // sm[r][p] = channels (2r,2r+1), pixel p

    int tb   = blockIdx.x;           // 0 .. BCHUNK*512-1
    int b    = b_base + (tb >> 9);   // 512 blocks per batch
    int base = (tb & 511) * 512;     // pixel base within batch
    int t = threadIdx.x;

#pragma unroll
    for (int q = 0; q < 4; q++) {
        int p = t + 128 * q;
        size_t gp = (size_t)b * HW + base + p;
        uint4 a  = __ldcs((const uint4*)(s + gp * 4));               // ch 0..7
        uint4 bq = __ldcs((const uint4*)(s + HI_OFF_H2 + gp * 4));   // ch 8..15
        sm[0][p] = *(__half2*)&a.x;  sm[1][p] = *(__half2*)&a.y;
        sm[2][p] = *(__half2*)&a.z;  sm[3][p] = *(__half2*)&a.w;
        sm[4][p] = *(__half2*)&bq.x; sm[5][p] = *(__half2*)&bq.y;
        sm[6][p] = *(__half2*)&bq.z; sm[7][p] = *(__half2*)&bq.w;
    }
    __syncthreads();

    float* ob = out + (size_t)b * CHW + base;

#pragma unroll
    for (int r = 0; r < 8; r++) {
        uint4 raw = *(const uint4*)&sm[r][4 * t];   // 4 half2 of channel pair r
        float2 f0 = __half22float2(*(__half2*)&raw.x);
        float2 f1 = __half22float2(*(__half2*)&raw.y);
        float2 f2 = __half22float2(*(__half2*)&raw.z);
        float2 f3 = __half22float2(*(__half2*)&raw.w);
        float4 ve = make_float4(f0.x, f1.x, f2.x, f3.x);  // channel 2r
        float4 vo = make_float4(f0.y, f1.y, f2.y, f3.y);  // channel 2r+1
        __stcs((float4*)(ob + (size_t)(2*r)     * HW) + t, ve);
        __stcs((float4*)(ob + (size_t)(2*r + 1) * HW) + t, vo);
    }
}

extern "C" void kernel_launch(void* const* d_in, const int* in_sizes, int n_in,
                              void* d_out, int out_size) {
    const float*  x    = (const float*)d_in[0];
    const float2* grid = (const float2*)d_in[1];
    float*        out  = (float*)d_out;

    static __half* scratch_ptr = nullptr;
    if (!scratch_ptr) cudaGetSymbolAddress((void**)&scratch_ptr, g_scratch);

    cudaLaunchAttribute attr[1];
    attr[0].id = cudaLaunchAttributeProgrammaticStreamSerialization;
    attr[0].val.programmaticStreamSerializationAllowed = 1;

    cudaLaunchConfig_t cfg{};
    cfg.stream   = 0;
    cfg.attrs    = attr;
    cfg.numAttrs = 1;

    // zero scratch (triggers dependents at entry -> S0 prologue overlaps it)
    zero_kernel<<<2048, 256>>>((uint4*)scratch_ptr);

    // PDL chain: S0, T0, S1, T1.
    //   T_k launches at S_k completion (S never triggers early).
    //   S1 launches at T0's entry-trigger -> overlaps T0's DRAM writes.
    for (int k = 0; k < 2; k++) {
        int b_base = k * BCHUNK;

        cfg.gridDim  = dim3(CHUNK_PIX / 256);    // 4096 blocks: full chip
        cfg.blockDim = dim3(256);
        cudaLaunchKernelEx(&cfg, splat_kernel, x, grid, b_base, (int)(k == 0));

        cfg.gridDim  = dim3(BCHUNK * 512);       // 2048 blocks
        cfg.blockDim = dim3(128);
        cudaLaunchKernelEx(&cfg, transpose_kernel,
                           (const __half2*)scratch_ptr, out, b_base);
    }
}

// round 13
// speedup vs baseline: 1.1762x; 1.0313x over previous
#include <cuda_runtime.h>
#include <cuda_fp16.h>
#include <cstdint>

// Problem shape (fixed by the dataset)
constexpr int B = 8, C = 16, H = 512, W = 512;
constexpr int HW = H * W;            // 262144 = 2^18
constexpr int CHW = C * HW;
constexpr int NPIX = B * HW;         // 2,097,152
constexpr int NOUT = B * CHW;        // 33,554,432

// Split-plane fp16 scratch, 64 MiB total (R10 layout):
//   plane LO = channels 0..7  : pixel p at 16B offset p*16
//   plane HI = channels 8..15 : same indexing, +32 MiB
__device__ __half g_scratch[NOUT];
constexpr size_t HI_OFF_H2 = (size_t)NPIX * 4;   // half2 offset of HI plane

// ---------------------------------------------------------------------------
// 16-byte fp16 vector reduction (hard max RED width): 8 halves per request.
// ---------------------------------------------------------------------------
__device__ __forceinline__ void red_v4h2(__half2* p, __half2 a, __half2 b,
                                         __half2 c, __half2 d) {
    unsigned ra = *(unsigned*)&a, rb = *(unsigned*)&b;
    unsigned rc = *(unsigned*)&c, rd = *(unsigned*)&d;
    asm volatile("red.global.add.noftz.v4.f16x2 [%0], {%1, %2, %3, %4};"
                 :: "l"(p), "r"(ra), "r"(rb), "r"(rc), "r"(rd) : "memory");
}

// ---------------------------------------------------------------------------
// Inverse bilinear splat into split-plane scratch (monolithic, R10 body).
// __launch_bounds__(256, 8): cap regs at 32 -> 8 blocks/SM -> ~full occupancy.
// The splat is L1tex-wavefront / MLP limited, so resident-warp count directly
// sets the sustained RED rate (R1: occ 95% -> L2 90%; R12: occ 68% -> L2 72%).
// ---------------------------------------------------------------------------
__global__ __launch_bounds__(256, 8)
void splat_kernel(const float* __restrict__ x,
                  const float2* __restrict__ grid) {
    int idx = blockIdx.x * 256 + threadIdx.x;

    int b  = idx >> 18;        // / HW
    int hw = idx & (HW - 1);   // % HW

    float2 g = __ldcs(grid + idx);   // single-use: evict-first

    float gi = fminf(fmaxf((g.x + 1.0f) * 0.5f * (float)H + 1.0f, 0.0f), (float)(H + 1));
    float gj = fminf(fmaxf((g.y + 1.0f) * 0.5f * (float)W + 1.0f, 0.0f), (float)(W + 1));

    int   fi  = (int)gi;            // gi >= 0 so trunc == floor
    int   fj  = (int)gj;
    float fri = gi - (float)fi;
    float frj = gj - (float)fj;

    float w00 = (1.0f - fri) * (1.0f - frj);
    float w01 = (1.0f - fri) * frj;
    float w10 = fri * (1.0f - frj);
    float w11 = fri * frj;

    int oi0 = fi - 1;
    int oj0 = fj - 1;
    bool i0 = (unsigned)oi0       < (unsigned)H;
    bool i1 = (unsigned)(oi0 + 1) < (unsigned)H;
    bool j0 = (unsigned)oj0       < (unsigned)W;
    bool j1 = (unsigned)(oj0 + 1) < (unsigned)W;

    // 16 channel values, coalesced per channel, streaming (single use)
    const float* xp = x + (size_t)b * CHW + hw;
    float v[C];
#pragma unroll
    for (int c = 0; c < C; c++) v[c] = __ldcs(xp + c * HW);

    // Plane pointers for corner (oi0, oj0); pixel stride = 4 half2 (16B).
    size_t p00 = (size_t)b * HW + (size_t)oi0 * W + oj0;
    __half2* l00 = (__half2*)g_scratch + p00 * 4;              // LO, (i0,j0)
    __half2* l10 = l00 + (size_t)W * 4;                        // LO, (i1,j0)
    __half2* h00 = (__half2*)g_scratch + HI_OFF_H2 + p00 * 4;  // HI: +32MB
    __half2* h10 = h00 + (size_t)W * 4;

#define PACK4(dst, wgt, half)                                                   \
    {                                                                           \
        _Pragma("unroll")                                                       \
        for (int j = 0; j < 4; j++)                                             \
            dst[j] = __floats2half2_rn(v[8*(half) + 2*j]     * (wgt),           \
                                       v[8*(half) + 2*j + 1] * (wgt));          \
    }

    if (j0) {   // corners (i0,j0)/(i1,j0): plane- and i-alternated issue
        __half2 a[4], c[4];
        if (i0) { PACK4(a, w00, 0); red_v4h2(l00, a[0], a[1], a[2], a[3]); }
        if (i1) { PACK4(c, w10, 0); red_v4h2(l10, c[0], c[1], c[2], c[3]); }
        if (i0) { PACK4(a, w00, 1); red_v4h2(h00, a[0], a[1], a[2], a[3]); }
        if (i1) { PACK4(c, w10, 1); red_v4h2(h10, c[0], c[1], c[2], c[3]); }
    }
    if (j1) {   // corners (i0,j1)/(i1,j1): next pixel = +4 half2 (16B)
        __half2 a[4], c[4];
        if (i0) { PACK4(a, w01, 0); red_v4h2(l00 + 4, a[0], a[1], a[2], a[3]); }
        if (i1) { PACK4(c, w11, 0); red_v4h2(l10 + 4, c[0], c[1], c[2], c[3]); }
        if (i0) { PACK4(a, w01, 1); red_v4h2(h00 + 4, a[0], a[1], a[2], a[3]); }
        if (i1) { PACK4(c, w11, 1); red_v4h2(h10 + 4, c[0], c[1], c[2], c[3]); }
    }
#undef PACK4
}

// ---------------------------------------------------------------------------
// Transpose split-plane fp16 scratch -> f32 out (B,C,H,W).
// 256 threads / 512-pixel tile (was 128): 8 blocks x 256 = 2048 threads/SM
// (full occupancy) and 8 float4 stores per thread -> better store-issue MLP.
// ---------------------------------------------------------------------------
__global__ __launch_bounds__(256)
void transpose_kernel(const __half2* __restrict__ s, float* __restrict__ out) {
    __shared__ __half2 sm[8][512];   // sm[r][p] = channels (2r,2r+1) of pixel p

    int base = blockIdx.x * 512;
    int t = threadIdx.x;

    // Load phase: 256 threads x 2 pixels, two 16B reads (LO/HI plane) each.
#pragma unroll
    for (int q = 0; q < 2; q++) {
        int p = t + 256 * q;
        uint4 a  = __ldcs((const uint4*)(s + (size_t)(base + p) * 4));             // ch 0..7
        uint4 bq = __ldcs((const uint4*)(s + HI_OFF_H2 + (size_t)(base + p) * 4)); // ch 8..15
        sm[0][p] = *(__half2*)&a.x;  sm[1][p] = *(__half2*)&a.y;
        sm[2][p] = *(__half2*)&a.z;  sm[3][p] = *(__half2*)&a.w;
        sm[4][p] = *(__half2*)&bq.x; sm[5][p] = *(__half2*)&bq.y;
        sm[6][p] = *(__half2*)&bq.z; sm[7][p] = *(__half2*)&bq.w;
    }
    __syncthreads();

    int b  = base >> 18;
    int hw = base & (HW - 1);
    float* ob = out + (size_t)b * CHW + hw;

    // Store phase: sub 0 handles channel pairs 0..3, sub 1 handles 4..7.
    int sub = t >> 7;                // 0 or 1
    int tt  = t & 127;               // pixel-quad index

#pragma unroll
    for (int r2 = 0; r2 < 4; r2++) {
        int r = sub * 4 + r2;
        uint4 raw = *(const uint4*)&sm[r][4 * tt];  // 4 half2 of channel pair r
        float2 f0 = __half22float2(*(__half2*)&raw.x);
        float2 f1 = __half22float2(*(__half2*)&raw.y);
        float2 f2 = __half22float2(*(__half2*)&raw.z);
        float2 f3 = __half22float2(*(__half2*)&raw.w);
        float4 ve = make_float4(f0.x, f1.x, f2.x, f3.x);  // channel 2r
        float4 vo = make_float4(f0.y, f1.y, f2.y, f3.y);  // channel 2r+1
        __stcs((float4*)(ob + (size_t)(2*r)     * HW) + tt, ve);
        __stcs((float4*)(ob + (size_t)(2*r + 1) * HW) + tt, vo);
    }
}

extern "C" void kernel_launch(void* const* d_in, const int* in_sizes, int n_in,
                              void* d_out, int out_size) {
    const float*  x    = (const float*)d_in[0];
    const float2* grid = (const float2*)d_in[1];
    float*        out  = (float*)d_out;

    static __half* scratch_ptr = nullptr;
    if (!scratch_ptr) cudaGetSymbolAddress((void**)&scratch_ptr, g_scratch);

    // 1) zero the fp16 scratch (standalone pure-write pass: cheapest form)
    cudaMemsetAsync(scratch_ptr, 0, (size_t)NOUT * sizeof(__half), 0);

    // 2) splat: 8 x 16B REDs per pixel, full occupancy (regs capped at 32)
    splat_kernel<<<NPIX / 256, 256>>>(x, grid);

    // 3) transpose split-plane scratch into f32 (B,C,H,W) output
    transpose_kernel<<<NPIX / 512, 256>>>((const __half2*)scratch_ptr, out);
}